// round 5
// baseline (speedup 1.0000x reference)
#include <cuda_runtime.h>
#include <cstdint>

// StructAttentionLayer: B=16384, A=50, D=256, fp32. HBM-bound (873MB, read once).
// R5: ONE persistent CTA per SM, TRIPLE-buffered cp.async.bulk pipeline
// (156.7KB dyn SMEM). While computing tile k, tiles k+1 and k+2 are in
// flight, so the per-SM DRAM demand queue never drains during compute.

#define A_NUM 50
#define D_DIM 256
#define ALPHA 0.2f
#define TILE_BYTES (A_NUM * D_DIM * 4)          // 51200
#define ENT_BYTES  (D_DIM * 4)                  // 1024
#define BUF_BYTES  (TILE_BYTES + ENT_BYTES)     // 52224 (16B-mult, 128B-aligned)
#define BUF_FLOATS (BUF_BYTES / 4)              // 13056
#define NBUF 3
#define DYN_SMEM   (NBUF * BUF_BYTES)           // 156672

__device__ __forceinline__ void issue_tile_load(uint32_t buf_a, uint32_t mb,
                                                const float* __restrict__ attrs,
                                                const float* __restrict__ ent,
                                                long long b)
{
    asm volatile("mbarrier.arrive.expect_tx.shared.b64 _, [%0], %1;"
                 :: "r"(mb), "r"((uint32_t)BUF_BYTES) : "memory");
    asm volatile("cp.async.bulk.shared::cta.global.mbarrier::complete_tx::bytes "
                 "[%0], [%1], %2, [%3];"
                 :: "r"(buf_a), "l"(attrs + b * (A_NUM * D_DIM)),
                    "r"((uint32_t)TILE_BYTES), "r"(mb) : "memory");
    asm volatile("cp.async.bulk.shared::cta.global.mbarrier::complete_tx::bytes "
                 "[%0], [%1], %2, [%3];"
                 :: "r"(buf_a + TILE_BYTES), "l"(ent + b * D_DIM),
                    "r"((uint32_t)ENT_BYTES), "r"(mb) : "memory");
}

__global__ __launch_bounds__(256, 1)
void struct_attn_kernel(const float* __restrict__ attrs,
                        const float* __restrict__ ent,
                        const float* __restrict__ aa,
                        float* __restrict__ out,
                        int B)
{
    extern __shared__ __align__(128) float sm[];
    __shared__ float e_s[A_NUM + 2];
    __shared__ __align__(8) unsigned long long mbar[NBUF];

    const int t    = threadIdx.x;
    const int warp = t >> 5;
    const int lane = t & 31;
    const int G    = gridDim.x;

    uint32_t mba[NBUF];
#pragma unroll
    for (int i = 0; i < NBUF; i++)
        mba[i] = (uint32_t)__cvta_generic_to_shared(&mbar[i]);
    const uint32_t smbase = (uint32_t)__cvta_generic_to_shared(sm);

    if (t == 0) {
#pragma unroll
        for (int i = 0; i < NBUF; i++)
            asm volatile("mbarrier.init.shared.b64 [%0], 1;" :: "r"(mba[i]) : "memory");
    }
    __syncthreads();

    // Weight vectors live in registers for the whole run (2KB total in L2).
    const float4* aa4 = reinterpret_cast<const float4*>(aa);
    const float4 aw0 = aa4[lane];            // a_attr[ lane*4 ..]
    const float4 aw1 = aa4[32 + lane];       // a_attr[128+lane*4 ..]
    const float4 ew0 = aa4[64 + lane];       // a_ent
    const float4 ew1 = aa4[96 + lane];

    // Prologue: prefetch first NBUF tiles.
    if (t == 0) {
#pragma unroll
        for (int i = 0; i < NBUF; i++) {
            const long long b = (long long)blockIdx.x + (long long)i * G;
            if (b < B)
                issue_tile_load(smbase + i * BUF_BYTES, mba[i], attrs, ent, b);
        }
    }

    uint32_t ph0 = 0, ph1 = 0, ph2 = 0;
    int p = 0;
    for (long long b = blockIdx.x; b < B; b += G) {
        float* tile = sm + p * BUF_FLOATS;
        float* ents = tile + A_NUM * D_DIM;
        const uint32_t mb = mba[p];
        const uint32_t myph = (p == 0) ? ph0 : (p == 1) ? ph1 : ph2;

        // Wait for this buffer's TMA (acquire).
        asm volatile(
            "{\n\t"
            ".reg .pred P;\n\t"
            "WL%=:\n\t"
            "mbarrier.try_wait.parity.acquire.cta.shared::cta.b64 P, [%0], %1, 0x989680;\n\t"
            "@P bra WD%=;\n\t"
            "bra WL%=;\n\t"
            "WD%=:\n\t"
            "}" :: "r"(mb), "r"(myph) : "memory");
        if (p == 0) ph0 ^= 1; else if (p == 1) ph1 ^= 1; else ph2 ^= 1;

        // --- logits: warp w owns rows {w, w+8, ...} (row within one warp) ---
        const float4* tile4 = reinterpret_cast<const float4*>(tile);
#pragma unroll
        for (int i = 0; i < 7; i++) {
            const int a = warp + 8 * i;
            if (a < A_NUM) {
                const float4 v0 = tile4[a * 64 + lane];
                const float4 v1 = tile4[a * 64 + 32 + lane];
                float s = v0.x * aw0.x + v0.y * aw0.y + v0.z * aw0.z + v0.w * aw0.w
                        + v1.x * aw1.x + v1.y * aw1.y + v1.z * aw1.z + v1.w * aw1.w;
                s += __shfl_xor_sync(0xffffffffu, s, 16);
                s += __shfl_xor_sync(0xffffffffu, s, 8);
                s += __shfl_xor_sync(0xffffffffu, s, 4);
                s += __shfl_xor_sync(0xffffffffu, s, 2);
                s += __shfl_xor_sync(0xffffffffu, s, 1);
                if (lane == 0) e_s[a] = s;
            }
        }
        // --- entity dot (warp 7 has only 6 rows) ---
        if (warp == 7) {
            const float4* e4 = reinterpret_cast<const float4*>(ents);
            const float4 ev0 = e4[lane];
            const float4 ev1 = e4[32 + lane];
            float pd = ev0.x * ew0.x + ev0.y * ew0.y + ev0.z * ew0.z + ev0.w * ew0.w
                     + ev1.x * ew1.x + ev1.y * ew1.y + ev1.z * ew1.z + ev1.w * ew1.w;
            pd += __shfl_xor_sync(0xffffffffu, pd, 16);
            pd += __shfl_xor_sync(0xffffffffu, pd, 8);
            pd += __shfl_xor_sync(0xffffffffu, pd, 4);
            pd += __shfl_xor_sync(0xffffffffu, pd, 2);
            pd += __shfl_xor_sync(0xffffffffu, pd, 1);
            if (lane == 0) e_s[A_NUM] = pd;
        }
        __syncthreads();

        // --- leaky-relu + softmax over 50 (warp 0), scaled by A_NUM ---
        if (warp == 0) {
            const float ed = e_s[A_NUM];
            float x0 = e_s[lane] + ed;
            x0 = (x0 > 0.f) ? x0 : ALPHA * x0;
            float x1 = -1e30f;
            if (lane < A_NUM - 32) {
                x1 = e_s[lane + 32] + ed;
                x1 = (x1 > 0.f) ? x1 : ALPHA * x1;
            }
            float m = fmaxf(x0, x1);
            m = fmaxf(m, __shfl_xor_sync(0xffffffffu, m, 16));
            m = fmaxf(m, __shfl_xor_sync(0xffffffffu, m, 8));
            m = fmaxf(m, __shfl_xor_sync(0xffffffffu, m, 4));
            m = fmaxf(m, __shfl_xor_sync(0xffffffffu, m, 2));
            m = fmaxf(m, __shfl_xor_sync(0xffffffffu, m, 1));
            const float q0 = __expf(x0 - m);
            const float q1 = (lane < A_NUM - 32) ? __expf(x1 - m) : 0.f;
            float ssum = q0 + q1;
            ssum += __shfl_xor_sync(0xffffffffu, ssum, 16);
            ssum += __shfl_xor_sync(0xffffffffu, ssum, 8);
            ssum += __shfl_xor_sync(0xffffffffu, ssum, 4);
            ssum += __shfl_xor_sync(0xffffffffu, ssum, 2);
            ssum += __shfl_xor_sync(0xffffffffu, ssum, 1);
            const float inv = (float)A_NUM / ssum;
            e_s[lane] = q0 * inv;
            if (lane < A_NUM - 32) e_s[lane + 32] = q1 * inv;
        }
        __syncthreads();

        // --- weighted sum: thread t owns output column t (conflict-free) ---
        float a0 = 0.f, a1 = 0.f;
#pragma unroll
        for (int a = 0; a < A_NUM; a += 2) {
            a0 = fmaf(e_s[a],     tile[a * D_DIM + t],       a0);
            a1 = fmaf(e_s[a + 1], tile[(a + 1) * D_DIM + t], a1);
        }
        out[b * D_DIM + t] = a0 + a1;

        // All threads done reading buffer p before it is refilled.
        __syncthreads();

        if (t == 0) {
            const long long bn = b + (long long)NBUF * G;
            if (bn < B)
                issue_tile_load((uint32_t)__cvta_generic_to_shared(tile), mb,
                                attrs, ent, bn);
        }

        p = (p == NBUF - 1) ? 0 : p + 1;
    }
}

extern "C" void kernel_launch(void* const* d_in, const int* in_sizes, int n_in,
                              void* d_out, int out_size)
{
    const float* attrs = (const float*)d_in[0];   // [16384, 50, 256]
    const float* ent   = (const float*)d_in[1];   // [16384, 256]
    const float* aa    = (const float*)d_in[2];   // [512, 1]
    float* out         = (float*)d_out;           // [16384, 256]

    static int n_sm = 0;
    if (!n_sm) {
        cudaDeviceGetAttribute(&n_sm, cudaDevAttrMultiProcessorCount, 0);
        if (n_sm <= 0) n_sm = 148;
        cudaFuncSetAttribute(struct_attn_kernel,
                             cudaFuncAttributeMaxDynamicSharedMemorySize, DYN_SMEM);
    }

    const int B = in_sizes[1] / D_DIM;            // 16384
    struct_attn_kernel<<<n_sm, 256, DYN_SMEM>>>(attrs, ent, aa, out, B);
}

// round 6
// speedup vs baseline: 1.1846x; 1.1846x over previous
#include <cuda_runtime.h>
#include <cstdint>

// StructAttentionLayer: B=16384, A=50, D=256, fp32. HBM-bound (873MB, read once).
// R6: persistent 2 CTAs/SM, depth-2 cp.async.bulk pipeline with EARLY BUFFER
// RELEASE: logits pass copies each warp's rows into registers; the SMEM buffer
// is refilled (tile k+2) BEFORE softmax/weighted-sum, which run from registers
// with an 8KB partial-combine. DRAM demand queue never drains during compute.

#define A_NUM 50
#define D_DIM 256
#define ALPHA 0.2f
#define TILE_BYTES (A_NUM * D_DIM * 4)          // 51200
#define ENT_BYTES  (D_DIM * 4)                  // 1024
#define BUF_BYTES  (TILE_BYTES + ENT_BYTES)     // 52224
#define BUF_FLOATS (BUF_BYTES / 4)              // 13056
#define NBUF 2
#define DYN_SMEM   (NBUF * BUF_BYTES)           // 104448

__device__ __forceinline__ void issue_tile_load(uint32_t buf_a, uint32_t mb,
                                                const float* __restrict__ attrs,
                                                const float* __restrict__ ent,
                                                long long b)
{
    asm volatile("mbarrier.arrive.expect_tx.shared.b64 _, [%0], %1;"
                 :: "r"(mb), "r"((uint32_t)BUF_BYTES) : "memory");
    asm volatile("cp.async.bulk.shared::cta.global.mbarrier::complete_tx::bytes "
                 "[%0], [%1], %2, [%3];"
                 :: "r"(buf_a), "l"(attrs + b * (A_NUM * D_DIM)),
                    "r"((uint32_t)TILE_BYTES), "r"(mb) : "memory");
    asm volatile("cp.async.bulk.shared::cta.global.mbarrier::complete_tx::bytes "
                 "[%0], [%1], %2, [%3];"
                 :: "r"(buf_a + TILE_BYTES), "l"(ent + b * D_DIM),
                    "r"((uint32_t)ENT_BYTES), "r"(mb) : "memory");
}

__global__ __launch_bounds__(256, 2)
void struct_attn_kernel(const float* __restrict__ attrs,
                        const float* __restrict__ ent,
                        const float* __restrict__ aa,
                        float* __restrict__ out,
                        int B)
{
    extern __shared__ __align__(128) float sm[];
    __shared__ float e_s[A_NUM + 2];
    __shared__ float4 part[8][64];              // 8KB: warp partials (cols 0..255)
    __shared__ __align__(8) unsigned long long mbar[NBUF];

    const int t    = threadIdx.x;
    const int warp = t >> 5;
    const int lane = t & 31;
    const int G    = gridDim.x;

    const uint32_t mb0 = (uint32_t)__cvta_generic_to_shared(&mbar[0]);
    const uint32_t mb1 = (uint32_t)__cvta_generic_to_shared(&mbar[1]);
    const uint32_t smbase = (uint32_t)__cvta_generic_to_shared(sm);

    if (t == 0) {
        asm volatile("mbarrier.init.shared.b64 [%0], 1;" :: "r"(mb0) : "memory");
        asm volatile("mbarrier.init.shared.b64 [%0], 1;" :: "r"(mb1) : "memory");
    }
    __syncthreads();

    const float4* aa4 = reinterpret_cast<const float4*>(aa);
    const float4 aw0 = aa4[lane];            // a_attr cols 4*lane..
    const float4 aw1 = aa4[32 + lane];       // a_attr cols 128+4*lane..
    const float4 ew0 = aa4[64 + lane];       // a_ent
    const float4 ew1 = aa4[96 + lane];

    // Prologue: prefetch first 2 tiles.
    if (t == 0) {
#pragma unroll
        for (int i = 0; i < NBUF; i++) {
            const long long b = (long long)blockIdx.x + (long long)i * G;
            if (b < B)
                issue_tile_load(smbase + i * BUF_BYTES, i ? mb1 : mb0, attrs, ent, b);
        }
    }

    uint32_t ph0 = 0, ph1 = 0;
    int p = 0;
    for (long long b = blockIdx.x; b < B; b += G) {
        float* tile = sm + p * BUF_FLOATS;
        float* ents = tile + A_NUM * D_DIM;
        const uint32_t mb = p ? mb1 : mb0;
        const uint32_t myph = p ? ph1 : ph0;

        asm volatile(
            "{\n\t"
            ".reg .pred P;\n\t"
            "WL%=:\n\t"
            "mbarrier.try_wait.parity.acquire.cta.shared::cta.b64 P, [%0], %1, 0x989680;\n\t"
            "@P bra WD%=;\n\t"
            "bra WL%=;\n\t"
            "WD%=:\n\t"
            "}" :: "r"(mb), "r"(myph) : "memory");
        if (p) ph1 ^= 1; else ph0 ^= 1;

        // --- logits pass: warp w owns rows {w, w+8, ...}; rows pulled into
        //     REGISTERS so the buffer can be released right after this pass ---
        const float4* tile4 = reinterpret_cast<const float4*>(tile);
        float4 v0[7], v1[7];
#pragma unroll
        for (int i = 0; i < 7; i++) {
            const int a = warp + 8 * i;
            if (a < A_NUM) {
                v0[i] = tile4[a * 64 + lane];
                v1[i] = tile4[a * 64 + 32 + lane];
                float s = v0[i].x * aw0.x + v0[i].y * aw0.y + v0[i].z * aw0.z + v0[i].w * aw0.w
                        + v1[i].x * aw1.x + v1[i].y * aw1.y + v1[i].z * aw1.z + v1[i].w * aw1.w;
                s += __shfl_xor_sync(0xffffffffu, s, 16);
                s += __shfl_xor_sync(0xffffffffu, s, 8);
                s += __shfl_xor_sync(0xffffffffu, s, 4);
                s += __shfl_xor_sync(0xffffffffu, s, 2);
                s += __shfl_xor_sync(0xffffffffu, s, 1);
                if (lane == 0) e_s[a] = s;
            }
        }
        if (warp == 7) {
            const float4* e4 = reinterpret_cast<const float4*>(ents);
            const float4 ev0 = e4[lane];
            const float4 ev1 = e4[32 + lane];
            float pd = ev0.x * ew0.x + ev0.y * ew0.y + ev0.z * ew0.z + ev0.w * ew0.w
                     + ev1.x * ew1.x + ev1.y * ew1.y + ev1.z * ew1.z + ev1.w * ew1.w;
            pd += __shfl_xor_sync(0xffffffffu, pd, 16);
            pd += __shfl_xor_sync(0xffffffffu, pd, 8);
            pd += __shfl_xor_sync(0xffffffffu, pd, 4);
            pd += __shfl_xor_sync(0xffffffffu, pd, 2);
            pd += __shfl_xor_sync(0xffffffffu, pd, 1);
            if (lane == 0) e_s[A_NUM] = pd;
        }
        __syncthreads();   // all reads of buffer p complete; e_s visible

        // EARLY RELEASE: refill buffer p with tile k+2 while we do softmax+wsum.
        if (t == 0) {
            const long long bn = b + (long long)NBUF * G;
            if (bn < B)
                issue_tile_load((uint32_t)__cvta_generic_to_shared(tile), mb,
                                attrs, ent, bn);
        }

        // --- leaky-relu + softmax over 50 (warp 0), scaled by A_NUM ---
        if (warp == 0) {
            const float ed = e_s[A_NUM];
            float x0 = e_s[lane] + ed;
            x0 = (x0 > 0.f) ? x0 : ALPHA * x0;
            float x1 = -1e30f;
            if (lane < A_NUM - 32) {
                x1 = e_s[lane + 32] + ed;
                x1 = (x1 > 0.f) ? x1 : ALPHA * x1;
            }
            float m = fmaxf(x0, x1);
            m = fmaxf(m, __shfl_xor_sync(0xffffffffu, m, 16));
            m = fmaxf(m, __shfl_xor_sync(0xffffffffu, m, 8));
            m = fmaxf(m, __shfl_xor_sync(0xffffffffu, m, 4));
            m = fmaxf(m, __shfl_xor_sync(0xffffffffu, m, 2));
            m = fmaxf(m, __shfl_xor_sync(0xffffffffu, m, 1));
            const float q0 = __expf(x0 - m);
            const float q1 = (lane < A_NUM - 32) ? __expf(x1 - m) : 0.f;
            float ssum = q0 + q1;
            ssum += __shfl_xor_sync(0xffffffffu, ssum, 16);
            ssum += __shfl_xor_sync(0xffffffffu, ssum, 8);
            ssum += __shfl_xor_sync(0xffffffffu, ssum, 4);
            ssum += __shfl_xor_sync(0xffffffffu, ssum, 2);
            ssum += __shfl_xor_sync(0xffffffffu, ssum, 1);
            const float inv = (float)A_NUM / ssum;
            e_s[lane] = q0 * inv;
            if (lane < A_NUM - 32) e_s[lane + 32] = q1 * inv;
        }
        __syncthreads();   // weights ready; also part[] free from prev iter

        // --- weighted sum from REGISTERS; cross-warp combine via part[] ---
        float4 acc0 = make_float4(0.f, 0.f, 0.f, 0.f);
        float4 acc1 = make_float4(0.f, 0.f, 0.f, 0.f);
#pragma unroll
        for (int i = 0; i < 7; i++) {
            const int a = warp + 8 * i;
            if (a < A_NUM) {
                const float w = e_s[a];
                acc0.x = fmaf(w, v0[i].x, acc0.x);
                acc0.y = fmaf(w, v0[i].y, acc0.y);
                acc0.z = fmaf(w, v0[i].z, acc0.z);
                acc0.w = fmaf(w, v0[i].w, acc0.w);
                acc1.x = fmaf(w, v1[i].x, acc1.x);
                acc1.y = fmaf(w, v1[i].y, acc1.y);
                acc1.z = fmaf(w, v1[i].z, acc1.z);
                acc1.w = fmaf(w, v1[i].w, acc1.w);
            }
        }
        part[warp][lane]      = acc0;   // cols 4*lane..
        part[warp][32 + lane] = acc1;   // cols 128+4*lane..
        __syncthreads();

        // --- threads 0..63 reduce the 8 warp partials and store (STG.128) ---
        if (t < 64) {
            float4 r = part[0][t];
#pragma unroll
            for (int g = 1; g < 8; g++) {
                const float4 q = part[g][t];
                r.x += q.x; r.y += q.y; r.z += q.z; r.w += q.w;
            }
            reinterpret_cast<float4*>(out + b * D_DIM)[t] = r;
        }
        // No extra sync: next iter's first __syncthreads protects part[] reuse.

        p ^= 1;
    }
}

extern "C" void kernel_launch(void* const* d_in, const int* in_sizes, int n_in,
                              void* d_out, int out_size)
{
    const float* attrs = (const float*)d_in[0];   // [16384, 50, 256]
    const float* ent   = (const float*)d_in[1];   // [16384, 256]
    const float* aa    = (const float*)d_in[2];   // [512, 1]
    float* out         = (float*)d_out;           // [16384, 256]

    static int n_sm = 0;
    if (!n_sm) {
        cudaDeviceGetAttribute(&n_sm, cudaDevAttrMultiProcessorCount, 0);
        if (n_sm <= 0) n_sm = 148;
        cudaFuncSetAttribute(struct_attn_kernel,
                             cudaFuncAttributeMaxDynamicSharedMemorySize, DYN_SMEM);
    }

    const int B = in_sizes[1] / D_DIM;            // 16384
    struct_attn_kernel<<<2 * n_sm, 256, DYN_SMEM>>>(attrs, ent, aa, out, B);
}

// round 7
// speedup vs baseline: 1.2299x; 1.0382x over previous
#include <cuda_runtime.h>
#include <cstdint>

// StructAttentionLayer: B=16384, A=50, D=256, fp32. HBM-bound (873MB, read once).
// R7: NON-persistent (keeps hardware work-stealing stagger, which beat every
// persistent variant), but 2 tiles per CTA with both cp.async.bulk issued at
// CTA entry (depth-2 standing queue). Compute tile0 overlaps tile1's stream;
// CTA exit immediately injects the next CTA's 104KB of demand.

#define A_NUM 50
#define D_DIM 256
#define ALPHA 0.2f
#define TILE_BYTES (A_NUM * D_DIM * 4)          // 51200
#define ENT_BYTES  (D_DIM * 4)                  // 1024
#define BUF_BYTES  (TILE_BYTES + ENT_BYTES)     // 52224
#define BUF_FLOATS (BUF_BYTES / 4)              // 13056
#define DYN_SMEM   (2 * BUF_BYTES)              // 104448

__device__ __forceinline__ void issue_tile_load(uint32_t buf_a, uint32_t mb,
                                                const float* __restrict__ attrs,
                                                const float* __restrict__ ent,
                                                long long b)
{
    asm volatile("mbarrier.arrive.expect_tx.shared.b64 _, [%0], %1;"
                 :: "r"(mb), "r"((uint32_t)BUF_BYTES) : "memory");
    asm volatile("cp.async.bulk.shared::cta.global.mbarrier::complete_tx::bytes "
                 "[%0], [%1], %2, [%3];"
                 :: "r"(buf_a), "l"(attrs + b * (A_NUM * D_DIM)),
                    "r"((uint32_t)TILE_BYTES), "r"(mb) : "memory");
    asm volatile("cp.async.bulk.shared::cta.global.mbarrier::complete_tx::bytes "
                 "[%0], [%1], %2, [%3];"
                 :: "r"(buf_a + TILE_BYTES), "l"(ent + b * D_DIM),
                    "r"((uint32_t)ENT_BYTES), "r"(mb) : "memory");
}

__global__ __launch_bounds__(256, 2)
void struct_attn_kernel(const float* __restrict__ attrs,
                        const float* __restrict__ ent,
                        const float* __restrict__ aa,
                        float* __restrict__ out)
{
    extern __shared__ __align__(128) float sm[];
    __shared__ float e_s[A_NUM + 2];
    __shared__ __align__(8) unsigned long long mbar[2];

    const int t    = threadIdx.x;
    const int warp = t >> 5;
    const int lane = t & 31;

    const uint32_t mb0 = (uint32_t)__cvta_generic_to_shared(&mbar[0]);
    const uint32_t mb1 = (uint32_t)__cvta_generic_to_shared(&mbar[1]);
    const uint32_t smbase = (uint32_t)__cvta_generic_to_shared(sm);

    const long long b0 = 2LL * blockIdx.x;

    // t0: init both mbarriers and fire BOTH tile loads before any barrier.
    if (t == 0) {
        asm volatile("mbarrier.init.shared.b64 [%0], 1;" :: "r"(mb0) : "memory");
        asm volatile("mbarrier.init.shared.b64 [%0], 1;" :: "r"(mb1) : "memory");
        asm volatile("fence.proxy.async.shared::cta;" ::: "memory");
        issue_tile_load(smbase,             mb0, attrs, ent, b0);
        issue_tile_load(smbase + BUF_BYTES, mb1, attrs, ent, b0 + 1);
    }

    // Weight vectors (2KB, L2-resident) — overlaps TMA latency.
    const float4* aa4 = reinterpret_cast<const float4*>(aa);
    const float4 aw0 = aa4[lane];            // a_attr cols 4*lane..
    const float4 aw1 = aa4[32 + lane];       // a_attr cols 128+4*lane..
    const float4 ew0 = aa4[64 + lane];       // a_ent
    const float4 ew1 = aa4[96 + lane];

    __syncthreads();   // mbarrier init visible to all threads

#pragma unroll
    for (int k = 0; k < 2; k++) {
        float* tile = sm + k * BUF_FLOATS;
        float* ents = tile + A_NUM * D_DIM;
        const uint32_t mb = k ? mb1 : mb0;
        const long long b = b0 + k;

        // Wait for this buffer's TMA (phase 0, acquire).
        asm volatile(
            "{\n\t"
            ".reg .pred P;\n\t"
            "WL%=:\n\t"
            "mbarrier.try_wait.parity.acquire.cta.shared::cta.b64 P, [%0], 0, 0x989680;\n\t"
            "@P bra WD%=;\n\t"
            "bra WL%=;\n\t"
            "WD%=:\n\t"
            "}" :: "r"(mb) : "memory");

        // --- logits: warp w owns rows {w, w+8, ...} (row within one warp) ---
        const float4* tile4 = reinterpret_cast<const float4*>(tile);
#pragma unroll
        for (int i = 0; i < 7; i++) {
            const int a = warp + 8 * i;
            if (a < A_NUM) {
                const float4 v0 = tile4[a * 64 + lane];
                const float4 v1 = tile4[a * 64 + 32 + lane];
                float s = v0.x * aw0.x + v0.y * aw0.y + v0.z * aw0.z + v0.w * aw0.w
                        + v1.x * aw1.x + v1.y * aw1.y + v1.z * aw1.z + v1.w * aw1.w;
                s += __shfl_xor_sync(0xffffffffu, s, 16);
                s += __shfl_xor_sync(0xffffffffu, s, 8);
                s += __shfl_xor_sync(0xffffffffu, s, 4);
                s += __shfl_xor_sync(0xffffffffu, s, 2);
                s += __shfl_xor_sync(0xffffffffu, s, 1);
                if (lane == 0) e_s[a] = s;
            }
        }
        // --- entity dot (warp 7 has only 6 rows) ---
        if (warp == 7) {
            const float4* e4 = reinterpret_cast<const float4*>(ents);
            const float4 ev0 = e4[lane];
            const float4 ev1 = e4[32 + lane];
            float pd = ev0.x * ew0.x + ev0.y * ew0.y + ev0.z * ew0.z + ev0.w * ew0.w
                     + ev1.x * ew1.x + ev1.y * ew1.y + ev1.z * ew1.z + ev1.w * ew1.w;
            pd += __shfl_xor_sync(0xffffffffu, pd, 16);
            pd += __shfl_xor_sync(0xffffffffu, pd, 8);
            pd += __shfl_xor_sync(0xffffffffu, pd, 4);
            pd += __shfl_xor_sync(0xffffffffu, pd, 2);
            pd += __shfl_xor_sync(0xffffffffu, pd, 1);
            if (lane == 0) e_s[A_NUM] = pd;
        }
        __syncthreads();

        // --- leaky-relu + softmax over 50 (warp 0), scaled by A_NUM ---
        if (warp == 0) {
            const float ed = e_s[A_NUM];
            float x0 = e_s[lane] + ed;
            x0 = (x0 > 0.f) ? x0 : ALPHA * x0;
            float x1 = -1e30f;
            if (lane < A_NUM - 32) {
                x1 = e_s[lane + 32] + ed;
                x1 = (x1 > 0.f) ? x1 : ALPHA * x1;
            }
            float m = fmaxf(x0, x1);
            m = fmaxf(m, __shfl_xor_sync(0xffffffffu, m, 16));
            m = fmaxf(m, __shfl_xor_sync(0xffffffffu, m, 8));
            m = fmaxf(m, __shfl_xor_sync(0xffffffffu, m, 4));
            m = fmaxf(m, __shfl_xor_sync(0xffffffffu, m, 2));
            m = fmaxf(m, __shfl_xor_sync(0xffffffffu, m, 1));
            const float q0 = __expf(x0 - m);
            const float q1 = (lane < A_NUM - 32) ? __expf(x1 - m) : 0.f;
            float ssum = q0 + q1;
            ssum += __shfl_xor_sync(0xffffffffu, ssum, 16);
            ssum += __shfl_xor_sync(0xffffffffu, ssum, 8);
            ssum += __shfl_xor_sync(0xffffffffu, ssum, 4);
            ssum += __shfl_xor_sync(0xffffffffu, ssum, 2);
            ssum += __shfl_xor_sync(0xffffffffu, ssum, 1);
            const float inv = (float)A_NUM / ssum;
            e_s[lane] = q0 * inv;
            if (lane < A_NUM - 32) e_s[lane + 32] = q1 * inv;
        }
        __syncthreads();

        // --- weighted sum: thread t owns output column t (conflict-free) ---
        float a0 = 0.f, a1 = 0.f;
#pragma unroll
        for (int a = 0; a < A_NUM; a += 2) {
            a0 = fmaf(e_s[a],     tile[a * D_DIM + t],       a0);
            a1 = fmaf(e_s[a + 1], tile[(a + 1) * D_DIM + t], a1);
        }
        out[b * D_DIM + t] = a0 + a1;

        if (k == 0) __syncthreads();   // protect e_s before tile1's logits
    }
}

extern "C" void kernel_launch(void* const* d_in, const int* in_sizes, int n_in,
                              void* d_out, int out_size)
{
    const float* attrs = (const float*)d_in[0];   // [16384, 50, 256]
    const float* ent   = (const float*)d_in[1];   // [16384, 256]
    const float* aa    = (const float*)d_in[2];   // [512, 1]
    float* out         = (float*)d_out;           // [16384, 256]

    static int attr_set = 0;
    if (!attr_set) {
        cudaFuncSetAttribute(struct_attn_kernel,
                             cudaFuncAttributeMaxDynamicSharedMemorySize, DYN_SMEM);
        attr_set = 1;
    }

    const int B = in_sizes[1] / D_DIM;            // 16384
    struct_attn_kernel<<<B / 2, 256, DYN_SMEM>>>(attrs, ent, aa, out);
}

// round 8
// speedup vs baseline: 1.4302x; 1.1629x over previous
#include <cuda_runtime.h>
#include <cstdint>

// StructAttentionLayer: B=16384, A=50, D=256, fp32. HBM-bound (873MB, read once).
// R8 = R3 skeleton (non-persistent, 1 tile/CTA, 52KB SMEM, 4 slots/SM — the
// only shape that hit 85% DRAM) plus:
//  (a) TMA issued at CTA entry by t0 BEFORE __syncthreads (faster turnover)
//  (b) tile split into 2 chunks w/ separate mbarriers: logits on rows 0..23
//      start while rows 24..49 are still streaming (compute under stream)
//  (c) __stcs streaming stores for out (less L2 pollution of read stream)

#define A_NUM 50
#define D_DIM 256
#define ALPHA 0.2f
#define ROWS_A 24
#define CHUNKA_BYTES (ROWS_A * D_DIM * 4)               // 24576
#define CHUNKB_BYTES ((A_NUM - ROWS_A) * D_DIM * 4)     // 26624
#define ENT_BYTES    (D_DIM * 4)                        // 1024
#define TILE_BYTES   (A_NUM * D_DIM * 4)                // 51200
#define DYN_SMEM     (TILE_BYTES + ENT_BYTES)           // 52224

__global__ __launch_bounds__(256, 4)
void struct_attn_kernel(const float* __restrict__ attrs,
                        const float* __restrict__ ent,
                        const float* __restrict__ aa,
                        float* __restrict__ out)
{
    extern __shared__ __align__(128) float sm[];
    float* tile = sm;                          // tile[a*256 + d], rows 0..49
    float* ents = sm + A_NUM * D_DIM;          // ents[256]

    __shared__ float e_s[A_NUM + 2];
    __shared__ __align__(8) unsigned long long mbar[2];

    const int b    = blockIdx.x;
    const int t    = threadIdx.x;
    const int warp = t >> 5;
    const int lane = t & 31;

    const uint32_t mbA = (uint32_t)__cvta_generic_to_shared(&mbar[0]);
    const uint32_t mbB = (uint32_t)__cvta_generic_to_shared(&mbar[1]);
    const uint32_t tile_a = (uint32_t)__cvta_generic_to_shared(tile);

    // t0: init mbarriers and fire both chunk loads immediately (no barrier first).
    if (t == 0) {
        asm volatile("mbarrier.init.shared.b64 [%0], 1;" :: "r"(mbA) : "memory");
        asm volatile("mbarrier.init.shared.b64 [%0], 1;" :: "r"(mbB) : "memory");
        asm volatile("fence.proxy.async.shared::cta;" ::: "memory");

        const float* gsrc = attrs + (size_t)b * (A_NUM * D_DIM);
        // Chunk A: rows 0..23
        asm volatile("mbarrier.arrive.expect_tx.shared.b64 _, [%0], %1;"
                     :: "r"(mbA), "r"((uint32_t)CHUNKA_BYTES) : "memory");
        asm volatile("cp.async.bulk.shared::cta.global.mbarrier::complete_tx::bytes "
                     "[%0], [%1], %2, [%3];"
                     :: "r"(tile_a), "l"(gsrc),
                        "r"((uint32_t)CHUNKA_BYTES), "r"(mbA) : "memory");
        // Chunk B: rows 24..49 + entity row
        asm volatile("mbarrier.arrive.expect_tx.shared.b64 _, [%0], %1;"
                     :: "r"(mbB), "r"((uint32_t)(CHUNKB_BYTES + ENT_BYTES)) : "memory");
        asm volatile("cp.async.bulk.shared::cta.global.mbarrier::complete_tx::bytes "
                     "[%0], [%1], %2, [%3];"
                     :: "r"(tile_a + CHUNKA_BYTES), "l"(gsrc + ROWS_A * D_DIM),
                        "r"((uint32_t)CHUNKB_BYTES), "r"(mbB) : "memory");
        asm volatile("cp.async.bulk.shared::cta.global.mbarrier::complete_tx::bytes "
                     "[%0], [%1], %2, [%3];"
                     :: "r"(tile_a + TILE_BYTES), "l"(ent + (size_t)b * D_DIM),
                        "r"((uint32_t)ENT_BYTES), "r"(mbB) : "memory");
    }

    // Weight vectors (2KB, L2-resident) — loads overlap TMA latency.
    const float4* aa4 = reinterpret_cast<const float4*>(aa);
    const float4 aw0 = aa4[lane];            // a_attr cols 4*lane..
    const float4 aw1 = aa4[32 + lane];       // a_attr cols 128+4*lane..

    __syncthreads();   // mbarrier inits visible before any try_wait

    const float4* tile4 = reinterpret_cast<const float4*>(tile);

    // --- wait chunk A; logits rows w, w+8, w+16 (all < 24) ---
    asm volatile(
        "{\n\t"
        ".reg .pred P;\n\t"
        "WLA%=:\n\t"
        "mbarrier.try_wait.parity.acquire.cta.shared::cta.b64 P, [%0], 0, 0x989680;\n\t"
        "@P bra WDA%=;\n\t"
        "bra WLA%=;\n\t"
        "WDA%=:\n\t"
        "}" :: "r"(mbA) : "memory");

#pragma unroll
    for (int i = 0; i < 3; i++) {
        const int a = warp + 8 * i;
        const float4 v0 = tile4[a * 64 + lane];
        const float4 v1 = tile4[a * 64 + 32 + lane];
        float s = v0.x * aw0.x + v0.y * aw0.y + v0.z * aw0.z + v0.w * aw0.w
                + v1.x * aw1.x + v1.y * aw1.y + v1.z * aw1.z + v1.w * aw1.w;
        s += __shfl_xor_sync(0xffffffffu, s, 16);
        s += __shfl_xor_sync(0xffffffffu, s, 8);
        s += __shfl_xor_sync(0xffffffffu, s, 4);
        s += __shfl_xor_sync(0xffffffffu, s, 2);
        s += __shfl_xor_sync(0xffffffffu, s, 1);
        if (lane == 0) e_s[a] = s;
    }

    // --- wait chunk B; logits rows w+24, w+32, w+40, w+48 (<50) + entity ---
    asm volatile(
        "{\n\t"
        ".reg .pred P;\n\t"
        "WLB%=:\n\t"
        "mbarrier.try_wait.parity.acquire.cta.shared::cta.b64 P, [%0], 0, 0x989680;\n\t"
        "@P bra WDB%=;\n\t"
        "bra WLB%=;\n\t"
        "WDB%=:\n\t"
        "}" :: "r"(mbB) : "memory");

#pragma unroll
    for (int i = 3; i < 7; i++) {
        const int a = warp + 8 * i;
        if (a < A_NUM) {
            const float4 v0 = tile4[a * 64 + lane];
            const float4 v1 = tile4[a * 64 + 32 + lane];
            float s = v0.x * aw0.x + v0.y * aw0.y + v0.z * aw0.z + v0.w * aw0.w
                    + v1.x * aw1.x + v1.y * aw1.y + v1.z * aw1.z + v1.w * aw1.w;
            s += __shfl_xor_sync(0xffffffffu, s, 16);
            s += __shfl_xor_sync(0xffffffffu, s, 8);
            s += __shfl_xor_sync(0xffffffffu, s, 4);
            s += __shfl_xor_sync(0xffffffffu, s, 2);
            s += __shfl_xor_sync(0xffffffffu, s, 1);
            if (lane == 0) e_s[a] = s;
        }
    }
    if (warp == 7) {
        const float4* e4 = reinterpret_cast<const float4*>(ents);
        const float4 ev0 = e4[lane];
        const float4 ev1 = e4[32 + lane];
        const float4 ew0 = aa4[64 + lane];   // a_ent
        const float4 ew1 = aa4[96 + lane];
        float pd = ev0.x * ew0.x + ev0.y * ew0.y + ev0.z * ew0.z + ev0.w * ew0.w
                 + ev1.x * ew1.x + ev1.y * ew1.y + ev1.z * ew1.z + ev1.w * ew1.w;
        pd += __shfl_xor_sync(0xffffffffu, pd, 16);
        pd += __shfl_xor_sync(0xffffffffu, pd, 8);
        pd += __shfl_xor_sync(0xffffffffu, pd, 4);
        pd += __shfl_xor_sync(0xffffffffu, pd, 2);
        pd += __shfl_xor_sync(0xffffffffu, pd, 1);
        if (lane == 0) e_s[A_NUM] = pd;
    }
    __syncthreads();

    // --- leaky-relu + softmax over 50 (warp 0), scaled by A_NUM ---
    if (warp == 0) {
        const float ed = e_s[A_NUM];
        float x0 = e_s[lane] + ed;
        x0 = (x0 > 0.f) ? x0 : ALPHA * x0;
        float x1 = -1e30f;
        if (lane < A_NUM - 32) {
            x1 = e_s[lane + 32] + ed;
            x1 = (x1 > 0.f) ? x1 : ALPHA * x1;
        }
        float m = fmaxf(x0, x1);
        m = fmaxf(m, __shfl_xor_sync(0xffffffffu, m, 16));
        m = fmaxf(m, __shfl_xor_sync(0xffffffffu, m, 8));
        m = fmaxf(m, __shfl_xor_sync(0xffffffffu, m, 4));
        m = fmaxf(m, __shfl_xor_sync(0xffffffffu, m, 2));
        m = fmaxf(m, __shfl_xor_sync(0xffffffffu, m, 1));
        const float q0 = __expf(x0 - m);
        const float q1 = (lane < A_NUM - 32) ? __expf(x1 - m) : 0.f;
        float ssum = q0 + q1;
        ssum += __shfl_xor_sync(0xffffffffu, ssum, 16);
        ssum += __shfl_xor_sync(0xffffffffu, ssum, 8);
        ssum += __shfl_xor_sync(0xffffffffu, ssum, 4);
        ssum += __shfl_xor_sync(0xffffffffu, ssum, 2);
        ssum += __shfl_xor_sync(0xffffffffu, ssum, 1);
        const float inv = (float)A_NUM / ssum;
        e_s[lane] = q0 * inv;
        if (lane < A_NUM - 32) e_s[lane + 32] = q1 * inv;
    }
    __syncthreads();

    // --- weighted sum: thread t owns output column t (conflict-free LDS) ---
    float a0 = 0.f, a1 = 0.f;
#pragma unroll
    for (int a = 0; a < A_NUM; a += 2) {
        a0 = fmaf(e_s[a],     tile[a * D_DIM + t],       a0);
        a1 = fmaf(e_s[a + 1], tile[(a + 1) * D_DIM + t], a1);
    }
    __stcs(out + (size_t)b * D_DIM + t, a0 + a1);   // streaming store
}

extern "C" void kernel_launch(void* const* d_in, const int* in_sizes, int n_in,
                              void* d_out, int out_size)
{
    const float* attrs = (const float*)d_in[0];   // [16384, 50, 256]
    const float* ent   = (const float*)d_in[1];   // [16384, 256]
    const float* aa    = (const float*)d_in[2];   // [512, 1]
    float* out         = (float*)d_out;           // [16384, 256]

    static int attr_set = 0;
    if (!attr_set) {
        cudaFuncSetAttribute(struct_attn_kernel,
                             cudaFuncAttributeMaxDynamicSharedMemorySize, DYN_SMEM);
        attr_set = 1;
    }

    const int B = in_sizes[1] / D_DIM;            // 16384
    struct_attn_kernel<<<B, 256, DYN_SMEM>>>(attrs, ent, aa, out);
}